// round 11
// baseline (speedup 1.0000x reference)
#include <cuda_runtime.h>
#include <cuda_bf16.h>
#include <mma.h>
#include <cstdint>

using namespace nvcuda;

// ---------------- problem constants ----------------
#define BATCH 4
#define SEQ 8192
#define DM 1024
#define NH 16
#define HD 64
#define NCHUNK 32
#define MTOT (BATCH * SEQ) // 32768

// ---------------- scratch (device globals; no allocs) ----------------
__device__ float g_q[MTOT * DM];
__device__ float g_k[MTOT * DM];
__device__ float g_v[MTOT * DM];
__device__ __nv_bfloat16 g_ah[MTOT * DM]; // hi split of x, later of attn-out
__device__ __nv_bfloat16 g_al[MTOT * DM]; // lo split
__device__ __nv_bfloat16 g_wh[4 * DM * DM]; // transposed weights hi (q,k,v,o)
__device__ __nv_bfloat16 g_wl[4 * DM * DM]; // transposed weights lo

__device__ __forceinline__ void split1(float x, __nv_bfloat16& h, __nv_bfloat16& l) {
    h = __float2bfloat16_rn(x);
    l = __float2bfloat16_rn(x - __bfloat162float(h));
}

// ===========================================================================
// prep: split fp32 -> bf16 hi/lo
// ===========================================================================
__global__ __launch_bounds__(256) void splitx_kernel(
    const float4* __restrict__ in, __nv_bfloat162* __restrict__ h,
    __nv_bfloat162* __restrict__ l)
{
    size_t i = (size_t)blockIdx.x * 256 + threadIdx.x;
    float4 v = in[i];
    __nv_bfloat16 h0, h1, h2, h3, l0, l1, l2, l3;
    split1(v.x, h0, l0); split1(v.y, h1, l1);
    split1(v.z, h2, l2); split1(v.w, h3, l3);
    __nv_bfloat162 a; a.x = h0; a.y = h1;
    __nv_bfloat162 b; b.x = h2; b.y = h3;
    __nv_bfloat162 c; c.x = l0; c.y = l1;
    __nv_bfloat162 d; d.x = l2; d.y = l3;
    h[2 * i] = a; h[2 * i + 1] = b;
    l[2 * i] = c; l[2 * i + 1] = d;
}

// ===========================================================================
// prep: W[K,N] fp32 -> Wt[N,K] bf16 hi/lo, 4 mats in one launch (blockIdx.z)
// ===========================================================================
__global__ __launch_bounds__(256) void wtrans_kernel(
    const float* __restrict__ W0, const float* __restrict__ W1,
    const float* __restrict__ W2, const float* __restrict__ W3,
    __nv_bfloat16* __restrict__ th, __nv_bfloat16* __restrict__ tl)
{
    __shared__ float tile[32][33];
    const int mat = blockIdx.z;
    const float* W = (mat == 0) ? W0 : (mat == 1) ? W1 : (mat == 2) ? W2 : W3;
    __nv_bfloat16* thm = th + (size_t)mat * DM * DM;
    __nv_bfloat16* tlm = tl + (size_t)mat * DM * DM;

    const int n0 = blockIdx.x * 32, k0 = blockIdx.y * 32;
    const int tx = threadIdx.x, ty = threadIdx.y;
    for (int r = ty; r < 32; r += 8)
        tile[r][tx] = W[(size_t)(k0 + r) * DM + n0 + tx];
    __syncthreads();
    for (int r = ty; r < 32; r += 8) {
        float v = tile[tx][r];
        __nv_bfloat16 h, l;
        split1(v, h, l);
        size_t o = (size_t)(n0 + r) * DM + k0 + tx;
        thm[o] = h;
        tlm[o] = l;
    }
}

// ===========================================================================
// GEMM, occupancy-fixed per R10 profile (regs=252 -> occ 12.5%, tensor 45%):
// Tile 64x128, BK=64, 256 threads, warp grid 2x4, WARP TILE 32x32
// (acc[2][2]=32 regs; transient al/bl frags) -> fits 128-reg cap at
// __launch_bounds__(256,2) -> 2 CTAs/SM -> 16 warps resident.
// Sync batched LDG->STS (the only load style that is fast on this chip).
// ===========================================================================
#define BKC 64
#define NCH2 (DM / BKC) // 16
#define SSTRIDE 72
// As_h 64x72 | As_l 64x72 | Bs_h 128x72 | Bs_l 128x72  (bf16)
#define GEMM_SMEM ((64 + 64 + 128 + 128) * SSTRIDE * 2) // 55296 B

__global__ __launch_bounds__(256, 2) void gemm_tc(
    const __nv_bfloat16* __restrict__ Ahg, const __nv_bfloat16* __restrict__ Alg,
    const __nv_bfloat16* __restrict__ Bhg, const __nv_bfloat16* __restrict__ Blg,
    float* __restrict__ C)
{
    extern __shared__ char smem[];
    __nv_bfloat16* As_h = reinterpret_cast<__nv_bfloat16*>(smem);
    __nv_bfloat16* As_l = As_h + 64 * SSTRIDE;
    __nv_bfloat16* Bs_h = As_l + 64 * SSTRIDE;
    __nv_bfloat16* Bs_l = Bs_h + 128 * SSTRIDE;

    const int tid = threadIdx.x;
    const int wid = tid >> 5;
    const int wm = wid >> 2; // 0..1 -> 32-row block
    const int wn = wid & 3;  // 0..3 -> 32-col block
    const int bm = blockIdx.y * 64, bn = blockIdx.x * 128;

    const __nv_bfloat16* pAh = Ahg + (size_t)bm * DM;
    const __nv_bfloat16* pAl = Alg + (size_t)bm * DM;
    const __nv_bfloat16* pBh = Bhg + (size_t)bn * DM;
    const __nv_bfloat16* pBl = Blg + (size_t)bn * DM;

    wmma::fragment<wmma::accumulator, 16, 16, 16, float> acc[2][2];
#pragma unroll
    for (int i = 0; i < 2; i++)
#pragma unroll
        for (int j = 0; j < 2; j++)
            wmma::fill_fragment(acc[i][j], 0.0f);

#pragma unroll 1
    for (int c = 0; c < NCH2; c++) {
        const int kc = c * BKC;
        // ---- sync load: 3072 16B units, 12 per thread ----
#pragma unroll
        for (int p = 0; p < 12; p++) {
            const __nv_bfloat16* src;
            __nv_bfloat16* dst;
            int local;
            if (p < 2)      { src = pAh; dst = As_h; local = p * 256 + tid; }
            else if (p < 4) { src = pAl; dst = As_l; local = (p - 2) * 256 + tid; }
            else if (p < 8) { src = pBh; dst = Bs_h; local = (p - 4) * 256 + tid; }
            else            { src = pBl; dst = Bs_l; local = (p - 8) * 256 + tid; }
            const int row = local >> 3, u = local & 7;
            uint4 val = *reinterpret_cast<const uint4*>(
                src + (size_t)row * DM + kc + u * 8);
            *reinterpret_cast<uint4*>(dst + row * SSTRIDE + u * 8) = val;
        }
        __syncthreads();

#pragma unroll
        for (int ks = 0; ks < 4; ks++) {
            wmma::fragment<wmma::matrix_a, 16, 16, 16, __nv_bfloat16, wmma::row_major> ah[2];
            wmma::fragment<wmma::matrix_b, 16, 16, 16, __nv_bfloat16, wmma::col_major> bh[2];
#pragma unroll
            for (int i = 0; i < 2; i++)
                wmma::load_matrix_sync(ah[i], As_h + (wm * 32 + i * 16) * SSTRIDE + ks * 16, SSTRIDE);
#pragma unroll
            for (int j = 0; j < 2; j++)
                wmma::load_matrix_sync(bh[j], Bs_h + (wn * 32 + j * 16) * SSTRIDE + ks * 16, SSTRIDE);
            // hh
#pragma unroll
            for (int i = 0; i < 2; i++)
#pragma unroll
                for (int j = 0; j < 2; j++)
                    wmma::mma_sync(acc[i][j], ah[i], bh[j], acc[i][j]);
            // lh: Al x Bh (al transient)
            {
                wmma::fragment<wmma::matrix_a, 16, 16, 16, __nv_bfloat16, wmma::row_major> al[2];
#pragma unroll
                for (int i = 0; i < 2; i++)
                    wmma::load_matrix_sync(al[i], As_l + (wm * 32 + i * 16) * SSTRIDE + ks * 16, SSTRIDE);
#pragma unroll
                for (int i = 0; i < 2; i++)
#pragma unroll
                    for (int j = 0; j < 2; j++)
                        wmma::mma_sync(acc[i][j], al[i], bh[j], acc[i][j]);
            }
            // hl: Ah x Bl (bl transient)
            {
                wmma::fragment<wmma::matrix_b, 16, 16, 16, __nv_bfloat16, wmma::col_major> bl[2];
#pragma unroll
                for (int j = 0; j < 2; j++)
                    wmma::load_matrix_sync(bl[j], Bs_l + (wn * 32 + j * 16) * SSTRIDE + ks * 16, SSTRIDE);
#pragma unroll
                for (int i = 0; i < 2; i++)
#pragma unroll
                    for (int j = 0; j < 2; j++)
                        wmma::mma_sync(acc[i][j], ah[i], bl[j], acc[i][j]);
            }
        }
        __syncthreads();
    }

#pragma unroll
    for (int i = 0; i < 2; i++)
#pragma unroll
        for (int j = 0; j < 2; j++)
            wmma::store_matrix_sync(
                C + (size_t)(bm + wm * 32 + i * 16) * DM + bn + wn * 32 + j * 16,
                acc[i][j], DM, wmma::mem_row_major);
}

// ===========================================================================
// Chunked local attention: EXACT R4 version (116KB smem, 128 threads) —
// the configuration measured in the 3318us run. Overlay variant reverted
// (R10 A/B: +900us at face value).
// ===========================================================================
#define ATTN_SMEM_FLOATS (64 * 65 + 128 * 65 + 128 * 65 + 64 * 130)
#define ATTN_SMEM_BYTES (ATTN_SMEM_FLOATS * 4)

__global__ __launch_bounds__(128) void attn_kernel(
    const float* __restrict__ q, const float* __restrict__ k,
    const float* __restrict__ v, __nv_bfloat16* __restrict__ oh,
    __nv_bfloat16* __restrict__ ol)
{
    extern __shared__ float smemf[];
    float* Qs = smemf;            // [64][65]
    float* Ks = Qs + 64 * 65;     // [128][65]
    float* Vs = Ks + 128 * 65;    // [128][65]
    float* Ss = Vs + 128 * 65;    // [64][130]

    const int bid = blockIdx.x;
    const int rtile = bid & 3;
    const int head = (bid >> 2) & 15;
    const int chunk = (bid >> 6) & (NCHUNK - 1);
    const int b = bid >> 11;

    const int tid = threadIdx.x;
    const int c0 = rtile * 64 - 64;
    const size_t base = ((size_t)(b * SEQ + chunk * 256)) * DM + head * HD;

    for (int idx = tid; idx < 64 * 16; idx += 128) {
        int row = idx >> 4;
        int c = (idx & 15) << 2;
        float4 val = *reinterpret_cast<const float4*>(
            q + base + (size_t)(rtile * 64 + row) * DM + c);
        float* dst = Qs + row * 65 + c;
        dst[0] = val.x; dst[1] = val.y; dst[2] = val.z; dst[3] = val.w;
    }
    for (int idx = tid; idx < 128 * 16; idx += 128) {
        int row = idx >> 4;
        int c = (idx & 15) << 2;
        int jc = c0 + row;
        float4 kv = make_float4(0.f, 0.f, 0.f, 0.f);
        float4 vv = make_float4(0.f, 0.f, 0.f, 0.f);
        if (jc >= 0) {
            kv = *reinterpret_cast<const float4*>(k + base + (size_t)jc * DM + c);
            vv = *reinterpret_cast<const float4*>(v + base + (size_t)jc * DM + c);
        }
        float* dk = Ks + row * 65 + c;
        dk[0] = kv.x; dk[1] = kv.y; dk[2] = kv.z; dk[3] = kv.w;
        float* dv = Vs + row * 65 + c;
        dv[0] = vv.x; dv[1] = vv.y; dv[2] = vv.z; dv[3] = vv.w;
    }
    __syncthreads();

    {
        const int rg = tid >> 3;
        const int cg = tid & 7;
        float acc[4][16];
#pragma unroll
        for (int r = 0; r < 4; r++)
#pragma unroll
            for (int jj = 0; jj < 16; jj++) acc[r][jj] = 0.f;

        for (int d = 0; d < 64; d++) {
            float qv0 = Qs[rg * 65 + d];
            float qv1 = Qs[(rg + 16) * 65 + d];
            float qv2 = Qs[(rg + 32) * 65 + d];
            float qv3 = Qs[(rg + 48) * 65 + d];
#pragma unroll
            for (int jj = 0; jj < 16; jj++) {
                float kv = Ks[(cg + 8 * jj) * 65 + d];
                acc[0][jj] += qv0 * kv;
                acc[1][jj] += qv1 * kv;
                acc[2][jj] += qv2 * kv;
                acc[3][jj] += qv3 * kv;
            }
        }
        const float scale = 0.125f;
#pragma unroll
        for (int r = 0; r < 4; r++)
#pragma unroll
            for (int jj = 0; jj < 16; jj++)
                Ss[(rg + 16 * r) * 130 + cg + 8 * jj] = acc[r][jj] * scale;
    }
    __syncthreads();

    {
        const int i = tid >> 1;
        const int half = tid & 1;
        const int lo = (rtile == 0) ? 64 : i;
        const int hi = i + 64;
        float* row = Ss + i * 130 + half * 64;
        const int jbase = half * 64;

        float m = -1e30f;
#pragma unroll
        for (int jj = 0; jj < 64; jj++) {
            int j = jbase + jj;
            if (j >= lo && j <= hi) m = fmaxf(m, row[jj]);
        }
        m = fmaxf(m, __shfl_xor_sync(0xffffffffu, m, 1));

        float s = 0.f;
#pragma unroll
        for (int jj = 0; jj < 64; jj++) {
            int j = jbase + jj;
            float e = 0.f;
            if (j >= lo && j <= hi) {
                e = __expf(row[jj] - m);
                s += e;
            }
            row[jj] = e;
        }
        s += __shfl_xor_sync(0xffffffffu, s, 1);
        float inv = 1.0f / s;
#pragma unroll
        for (int jj = 0; jj < 64; jj++) row[jj] *= inv;
    }
    __syncthreads();

    {
        const int rg = tid >> 2;
        const int cg = tid & 3;
        float acc0[16], acc1[16];
#pragma unroll
        for (int dd = 0; dd < 16; dd++) { acc0[dd] = 0.f; acc1[dd] = 0.f; }

        for (int j = 0; j < 128; j++) {
            float p0 = Ss[rg * 130 + j];
            float p1 = Ss[(rg + 32) * 130 + j];
#pragma unroll
            for (int dd = 0; dd < 16; dd++) {
                float vv = Vs[j * 65 + cg * 16 + dd];
                acc0[dd] += p0 * vv;
                acc1[dd] += p1 * vv;
            }
        }
#pragma unroll
        for (int r = 0; r < 2; r++) {
            const float* accp = r ? acc1 : acc0;
            size_t off = base + (size_t)(rtile * 64 + rg + 32 * r) * DM + cg * 16;
#pragma unroll
            for (int d2 = 0; d2 < 8; d2++) {
                __nv_bfloat16 h0, h1, l0, l1;
                split1(accp[d2 * 2 + 0], h0, l0);
                split1(accp[d2 * 2 + 1], h1, l1);
                __nv_bfloat162 hp; hp.x = h0; hp.y = h1;
                __nv_bfloat162 lp; lp.x = l0; lp.y = l1;
                *reinterpret_cast<__nv_bfloat162*>(oh + off + d2 * 2) = hp;
                *reinterpret_cast<__nv_bfloat162*>(ol + off + d2 * 2) = lp;
            }
        }
    }
}

// ===========================================================================
// kernel_launch
// ===========================================================================
extern "C" void kernel_launch(void* const* d_in, const int* in_sizes, int n_in,
                              void* d_out, int out_size)
{
    (void)in_sizes; (void)n_in; (void)out_size;
    const float* x  = (const float*)d_in[0];
    const float* Wq = (const float*)d_in[1];
    const float* Wk = (const float*)d_in[2];
    const float* Wv = (const float*)d_in[3];
    const float* Wo = (const float*)d_in[4];
    float* out = (float*)d_out;

    float *q, *k, *v;
    __nv_bfloat16 *ah, *al, *wh, *wl;
    cudaGetSymbolAddress((void**)&q, g_q);
    cudaGetSymbolAddress((void**)&k, g_k);
    cudaGetSymbolAddress((void**)&v, g_v);
    cudaGetSymbolAddress((void**)&ah, g_ah);
    cudaGetSymbolAddress((void**)&al, g_al);
    cudaGetSymbolAddress((void**)&wh, g_wh);
    cudaGetSymbolAddress((void**)&wl, g_wl);

    cudaFuncSetAttribute(gemm_tc, cudaFuncAttributeMaxDynamicSharedMemorySize,
                         GEMM_SMEM);
    cudaFuncSetAttribute(attn_kernel, cudaFuncAttributeMaxDynamicSharedMemorySize,
                         ATTN_SMEM_BYTES);

    // 1) split x into bf16 hi/lo
    splitx_kernel<<<(MTOT * DM / 4) / 256, 256>>>(
        (const float4*)x, (__nv_bfloat162*)ah, (__nv_bfloat162*)al);

    // 2) transpose+split all four weights (one launch)
    dim3 wgrid(DM / 32, DM / 32, 4);
    dim3 wblk(32, 8);
    wtrans_kernel<<<wgrid, wblk>>>(Wq, Wk, Wv, Wo, wh, wl);

    // 3) Q/K/V projections (separate launches)
    dim3 ggrid(DM / 128, MTOT / 64); // (8, 512)
    gemm_tc<<<ggrid, 256, GEMM_SMEM>>>(ah, al, wh + 0 * (size_t)DM * DM, wl + 0 * (size_t)DM * DM, q);
    gemm_tc<<<ggrid, 256, GEMM_SMEM>>>(ah, al, wh + 1 * (size_t)DM * DM, wl + 1 * (size_t)DM * DM, k);
    gemm_tc<<<ggrid, 256, GEMM_SMEM>>>(ah, al, wh + 2 * (size_t)DM * DM, wl + 2 * (size_t)DM * DM, v);

    // 4) attention (writes bf16 hi/lo into ah/al)
    attn_kernel<<<BATCH * NCHUNK * NH * 4, 128, ATTN_SMEM_BYTES>>>(q, k, v, ah, al);

    // 5) output projection
    gemm_tc<<<ggrid, 256, GEMM_SMEM>>>(ah, al, wh + 3 * (size_t)DM * DM, wl + 3 * (size_t)DM * DM, out);
}